// round 1
// baseline (speedup 1.0000x reference)
#include <cuda_runtime.h>
#include <cuda_bf16.h>
#include <math.h>

// ---------------------------------------------------------------------------
// Problem constants
// ---------------------------------------------------------------------------
#define D_MODEL   1024
#define N_HEADS   16
#define N_KV      8
#define HEAD_DIM  64
#define HIDDEN    4096
#define BATCH     4
#define SEQ       2048
#define BT        (BATCH * SEQ)        // 8192 rows

// ---------------------------------------------------------------------------
// Scratch (device globals: allocation-free rule)
// ---------------------------------------------------------------------------
__device__ float g_h  [BT * D_MODEL];          // rmsnorm1 output
__device__ float g_q  [BT * D_MODEL];          // q  [b,t,h,d]
__device__ float g_k  [BT * N_KV * HEAD_DIM];  // k  [b,t,kh,d]
__device__ float g_v  [BT * N_KV * HEAD_DIM];  // v
__device__ float g_ao [BT * D_MODEL];          // attention output (pre-proj)
__device__ float g_h2 [BT * D_MODEL];          // rmsnorm2 output
__device__ float g_a  [BT * HIDDEN];           // w1 branch / silu*w2 product
__device__ float g_b  [BT * HIDDEN];           // w2 branch

// ---------------------------------------------------------------------------
// RMSNorm: one block per row (1024 elements), 256 threads
// ---------------------------------------------------------------------------
__global__ void rmsnorm_kernel(const float* __restrict__ x,
                               const float* __restrict__ g,
                               float* __restrict__ out) {
    const int row = blockIdx.x;
    const int tid = threadIdx.x;
    const float* xr = x + (long)row * D_MODEL;
    float4 v = *reinterpret_cast<const float4*>(xr + tid * 4);
    float s = v.x * v.x + v.y * v.y + v.z * v.z + v.w * v.w;

    // warp reduce
    #pragma unroll
    for (int off = 16; off > 0; off >>= 1)
        s += __shfl_xor_sync(0xffffffffu, s, off);

    __shared__ float red[8];
    if ((tid & 31) == 0) red[tid >> 5] = s;
    __syncthreads();
    float total;
    {
        float t = (tid < 8) ? red[tid] : 0.f;
        #pragma unroll
        for (int off = 4; off > 0; off >>= 1)
            t += __shfl_xor_sync(0xffffffffu, t, off);
        __shared__ float bc;
        if (tid == 0) bc = t;
        __syncthreads();
        total = bc;
    }
    float inv = rsqrtf(total * (1.0f / D_MODEL) + 1e-6f);
    float4 gv = *reinterpret_cast<const float4*>(g + tid * 4);
    float4 o;
    o.x = v.x * inv * gv.x;
    o.y = v.y * inv * gv.y;
    o.z = v.z * inv * gv.z;
    o.w = v.w * inv * gv.w;
    *reinterpret_cast<float4*>(out + (long)row * D_MODEL + tid * 4) = o;
}

// ---------------------------------------------------------------------------
// SGEMM: C[M,N] = A[M,K] @ B[K,N]  (+ residual R if epi)
// 64x64 tile, BK=16, 256 threads, 4x4 per thread.
// All dims divisible by 64 / 16 in this problem -> no bounds checks.
// ---------------------------------------------------------------------------
__global__ void __launch_bounds__(256)
sgemm_kernel(const float* __restrict__ A, const float* __restrict__ B,
             const float* __restrict__ R, float* __restrict__ C,
             int M, int N, int K, int epi) {
    __shared__ float As[16][64];
    __shared__ float Bs[16][64];

    const int tid = threadIdx.x;
    const int tx = tid & 15, ty = tid >> 4;
    const int m0 = blockIdx.y << 6, n0 = blockIdx.x << 6;

    const int arow = tid >> 2;             // 0..63
    const int acol = (tid & 3) << 2;       // 0,4,8,12
    const int brow = tid >> 4;             // 0..15
    const int bcol = (tid & 15) << 2;      // 0..60

    const float* Ap = A + (long)(m0 + arow) * K + acol;
    const float* Bp = B + (long)brow * N + n0 + bcol;

    float acc[4][4] = {};

    for (int k0 = 0; k0 < K; k0 += 16) {
        float4 av = *reinterpret_cast<const float4*>(Ap + k0);
        float4 bv = *reinterpret_cast<const float4*>(Bp + (long)k0 * N);
        As[acol + 0][arow] = av.x;
        As[acol + 1][arow] = av.y;
        As[acol + 2][arow] = av.z;
        As[acol + 3][arow] = av.w;
        *reinterpret_cast<float4*>(&Bs[brow][bcol]) = bv;
        __syncthreads();

        #pragma unroll
        for (int kk = 0; kk < 16; kk++) {
            float4 a4 = *reinterpret_cast<const float4*>(&As[kk][ty << 2]);
            float4 b4 = *reinterpret_cast<const float4*>(&Bs[kk][tx << 2]);
            float a[4] = {a4.x, a4.y, a4.z, a4.w};
            float b[4] = {b4.x, b4.y, b4.z, b4.w};
            #pragma unroll
            for (int i = 0; i < 4; i++)
                #pragma unroll
                for (int j = 0; j < 4; j++)
                    acc[i][j] += a[i] * b[j];
        }
        __syncthreads();
    }

    #pragma unroll
    for (int i = 0; i < 4; i++) {
        int row = m0 + (ty << 2) + i;
        long off = (long)row * N + n0 + (tx << 2);
        float4 o;
        o.x = acc[i][0]; o.y = acc[i][1]; o.z = acc[i][2]; o.w = acc[i][3];
        if (epi) {
            float4 r = *reinterpret_cast<const float4*>(R + off);
            o.x += r.x; o.y += r.y; o.z += r.z; o.w += r.w;
        }
        *reinterpret_cast<float4*>(C + off) = o;
    }
}

// ---------------------------------------------------------------------------
// RoPE (half-split, applied in place to q [b,t,16,64] and k [b,t,8,64])
// grid: BT blocks, 768 threads (512 for q heads, 256 for k heads)
// ---------------------------------------------------------------------------
__global__ void rope_kernel(float* __restrict__ q, float* __restrict__ k) {
    const int row = blockIdx.x;          // b*T + t
    const int t = row & (SEQ - 1);
    const int tid = threadIdx.x;

    float* ptr;
    int j;
    if (tid < 512) {
        int h = tid >> 5; j = tid & 31;
        ptr = q + (long)row * D_MODEL + h * HEAD_DIM;
    } else {
        int u = tid - 512;
        int h = u >> 5; j = u & 31;
        ptr = k + (long)row * (N_KV * HEAD_DIM) + h * HEAD_DIM;
    }
    // inv_freq = 10000^(-j/32)
    float inv = (float)exp(-(double)j / 32.0 * 9.210340371976184); // ln(10000)
    float fr = (float)t * inv;
    float c = cosf(fr), s = sinf(fr);
    float x1 = ptr[j], x2 = ptr[j + 32];
    ptr[j]      = x1 * c - x2 * s;
    ptr[j + 32] = x2 * c + x1 * s;
}

// ---------------------------------------------------------------------------
// Flash-style causal attention, GQA (q head h uses kv head h/2).
// Block = 128 threads = 128 query rows; loops 64-key tiles up to causal bound.
// Q row in registers, K/V tiles in smem (stride 65 pad), per-thread scores in
// local memory, online softmax with fp32 accumulators.
// ---------------------------------------------------------------------------
__global__ void __launch_bounds__(128)
attn_kernel(const float* __restrict__ q, const float* __restrict__ k,
            const float* __restrict__ v, float* __restrict__ o) {
    __shared__ float Ks[64 * 65];
    __shared__ float Vs[64 * 65];

    const int tid = threadIdx.x;
    const int t0  = blockIdx.x * 128;
    const int bh  = blockIdx.y;
    const int b   = bh >> 4;
    const int hq  = bh & 15;
    const int kvh = hq >> 1;
    const int t   = t0 + tid;

    // Q row -> registers (scaled by 1/sqrt(64))
    float qreg[64];
    {
        const float* qp = q + (long)(b * SEQ + t) * D_MODEL + hq * HEAD_DIM;
        #pragma unroll
        for (int d4 = 0; d4 < 16; d4++) {
            float4 vq = *reinterpret_cast<const float4*>(qp + d4 * 4);
            qreg[d4 * 4 + 0] = vq.x * 0.125f;
            qreg[d4 * 4 + 1] = vq.y * 0.125f;
            qreg[d4 * 4 + 2] = vq.z * 0.125f;
            qreg[d4 * 4 + 3] = vq.w * 0.125f;
        }
    }

    float acc[64];
    #pragma unroll
    for (int d = 0; d < 64; d++) acc[d] = 0.f;
    float m = -1e30f, l = 0.f;

    float sc[64];   // dynamic-indexed -> local memory (L1-backed), per-thread

    const int ntiles = (t0 >> 6) + 2;
    for (int it = 0; it < ntiles; it++) {
        const int s0 = it * 64;
        __syncthreads();
        // cooperative K/V tile load (coalesced: 64-float rows)
        for (int i = tid; i < 64 * 64; i += 128) {
            int r = i >> 6, d = i & 63;
            long base = (long)(b * SEQ + s0 + r) * (N_KV * HEAD_DIM) + kvh * HEAD_DIM + d;
            Ks[r * 65 + d] = k[base];
            Vs[r * 65 + d] = v[base];
        }
        __syncthreads();

        // pass 1: scores + tile max
        float tmax = -1e30f;
        for (int j = 0; j < 64; j++) {
            float s = 0.f;
            const float* kr = &Ks[j * 65];
            #pragma unroll
            for (int d = 0; d < 64; d++) s += qreg[d] * kr[d];
            s = (s0 + j <= t) ? s : -1e30f;
            sc[j] = s;
            tmax = fmaxf(tmax, s);
        }

        float mnew = fmaxf(m, tmax);
        float corr = expf(m - mnew);
        l *= corr;
        #pragma unroll
        for (int d = 0; d < 64; d++) acc[d] *= corr;

        // pass 2: exp + accumulate into acc
        for (int j = 0; j < 64; j++) {
            float p = expf(sc[j] - mnew);
            l += p;
            const float* vr = &Vs[j * 65];
            #pragma unroll
            for (int d = 0; d < 64; d++) acc[d] += p * vr[d];
        }
        m = mnew;
    }

    const float invl = 1.0f / l;
    float* op = o + (long)(b * SEQ + t) * D_MODEL + hq * HEAD_DIM;
    #pragma unroll
    for (int d4 = 0; d4 < 16; d4++) {
        float4 ov;
        ov.x = acc[d4 * 4 + 0] * invl;
        ov.y = acc[d4 * 4 + 1] * invl;
        ov.z = acc[d4 * 4 + 2] * invl;
        ov.w = acc[d4 * 4 + 3] * invl;
        *reinterpret_cast<float4*>(op + d4 * 4) = ov;
    }
}

// ---------------------------------------------------------------------------
// SiLU(a) * b  -> a  (in place)
// ---------------------------------------------------------------------------
__global__ void silu_mul_kernel(float* __restrict__ a,
                                const float* __restrict__ b, long n) {
    long i = (long)blockIdx.x * blockDim.x + threadIdx.x;
    long stride = (long)gridDim.x * blockDim.x;
    for (; i < n; i += stride) {
        float x = a[i];
        float s = x / (1.0f + expf(-x));
        a[i] = s * b[i];
    }
}

// ---------------------------------------------------------------------------
// Launch
// ---------------------------------------------------------------------------
extern "C" void kernel_launch(void* const* d_in, const int* in_sizes, int n_in,
                              void* d_out, int out_size) {
    const float* x  = (const float*)d_in[0];
    const float* g1 = (const float*)d_in[1];
    const float* g2 = (const float*)d_in[2];
    const float* wq = (const float*)d_in[3];
    const float* wk = (const float*)d_in[4];
    const float* wv = (const float*)d_in[5];
    const float* wo = (const float*)d_in[6];
    const float* w1 = (const float*)d_in[7];
    const float* w2 = (const float*)d_in[8];
    const float* w3 = (const float*)d_in[9];
    float* out = (float*)d_out;

    float *h, *q, *k, *v, *ao, *h2, *a, *bb;
    cudaGetSymbolAddress((void**)&h,  g_h);
    cudaGetSymbolAddress((void**)&q,  g_q);
    cudaGetSymbolAddress((void**)&k,  g_k);
    cudaGetSymbolAddress((void**)&v,  g_v);
    cudaGetSymbolAddress((void**)&ao, g_ao);
    cudaGetSymbolAddress((void**)&h2, g_h2);
    cudaGetSymbolAddress((void**)&a,  g_a);
    cudaGetSymbolAddress((void**)&bb, g_b);

    // 1. h = rmsnorm(x, g1)
    rmsnorm_kernel<<<BT, 256>>>(x, g1, h);

    // 2. q/k/v projections
    sgemm_kernel<<<dim3(D_MODEL / 64, BT / 64), 256>>>(h, wq, nullptr, q, BT, D_MODEL, D_MODEL, 0);
    sgemm_kernel<<<dim3((N_KV * HEAD_DIM) / 64, BT / 64), 256>>>(h, wk, nullptr, k, BT, N_KV * HEAD_DIM, D_MODEL, 0);
    sgemm_kernel<<<dim3((N_KV * HEAD_DIM) / 64, BT / 64), 256>>>(h, wv, nullptr, v, BT, N_KV * HEAD_DIM, D_MODEL, 0);

    // 3. RoPE in place
    rope_kernel<<<BT, 768>>>(q, k);

    // 4. causal GQA attention
    attn_kernel<<<dim3(SEQ / 128, BATCH * N_HEADS), 128>>>(q, k, v, ao);

    // 5. out-proj + residual: d_out = ao @ wo + x
    sgemm_kernel<<<dim3(D_MODEL / 64, BT / 64), 256>>>(ao, wo, x, out, BT, D_MODEL, D_MODEL, 1);

    // 6. h2 = rmsnorm(d_out, g2)
    rmsnorm_kernel<<<BT, 256>>>(out, g2, h2);

    // 7. FFN branches
    sgemm_kernel<<<dim3(HIDDEN / 64, BT / 64), 256>>>(h2, w1, nullptr, a,  BT, HIDDEN, D_MODEL, 0);
    sgemm_kernel<<<dim3(HIDDEN / 64, BT / 64), 256>>>(h2, w2, nullptr, bb, BT, HIDDEN, D_MODEL, 0);

    // 8. a = silu(a) * b
    silu_mul_kernel<<<2048, 256>>>(a, bb, (long)BT * HIDDEN);

    // 9. d_out += a @ w3
    sgemm_kernel<<<dim3(D_MODEL / 64, BT / 64), 256>>>(a, w3, out, out, BT, D_MODEL, HIDDEN, 1);
}

// round 3
// speedup vs baseline: 1.6125x; 1.6125x over previous
#include <cuda_runtime.h>
#include <cuda_bf16.h>
#include <math.h>
#include <stdint.h>

// ---------------------------------------------------------------------------
// Problem constants
// ---------------------------------------------------------------------------
#define D_MODEL   1024
#define N_HEADS   16
#define N_KV      8
#define HEAD_DIM  64
#define HIDDEN    4096
#define BATCH     4
#define SEQ       2048
#define BT        (BATCH * SEQ)        // 8192 rows

// ---------------------------------------------------------------------------
// Scratch (device globals: allocation-free rule)
// ---------------------------------------------------------------------------
__device__ float g_h  [BT * D_MODEL];
__device__ float g_q  [BT * D_MODEL];
__device__ float g_k  [BT * N_KV * HEAD_DIM];
__device__ float g_v  [BT * N_KV * HEAD_DIM];
__device__ float g_ao [BT * D_MODEL];
__device__ float g_h2 [BT * D_MODEL];
__device__ float g_a  [BT * HIDDEN];
__device__ float g_b  [BT * HIDDEN];

// transposed weights [N,K] (K contiguous) so B is K-major (col-major for mma)
__device__ float g_wqT[D_MODEL * D_MODEL];
__device__ float g_wkT[(N_KV * HEAD_DIM) * D_MODEL];
__device__ float g_wvT[(N_KV * HEAD_DIM) * D_MODEL];
__device__ float g_woT[D_MODEL * D_MODEL];
__device__ float g_w1T[HIDDEN * D_MODEL];
__device__ float g_w2T[HIDDEN * D_MODEL];
__device__ float g_w3T[D_MODEL * HIDDEN];

// ---------------------------------------------------------------------------
// Helpers
// ---------------------------------------------------------------------------
__device__ __forceinline__ uint32_t f2tf32(float x) {
    uint32_t r;
    asm("cvt.rna.tf32.f32 %0, %1;" : "=r"(r) : "f"(x));
    return r;
}

__device__ __forceinline__ void mma_tf32(float* c, const uint32_t* a, const uint32_t* b) {
    asm volatile(
        "mma.sync.aligned.m16n8k8.row.col.f32.tf32.tf32.f32 "
        "{%0,%1,%2,%3}, {%4,%5,%6,%7}, {%8,%9}, {%0,%1,%2,%3};\n"
        : "+f"(c[0]), "+f"(c[1]), "+f"(c[2]), "+f"(c[3])
        : "r"(a[0]), "r"(a[1]), "r"(a[2]), "r"(a[3]), "r"(b[0]), "r"(b[1]));
}

// ---------------------------------------------------------------------------
// tf32 tensor-core GEMM: C[M,N] = A[M,K] @ Bt[N,K]^T (+ residual R if epi)
// 128x128 CTA tile, BK=32, 256 threads (8 warps, each 32x64),
// double-buffered smem [128][36] (pad 4), GMEM prefetch in registers.
// M,N multiples of 128; K multiple of 32.
// ---------------------------------------------------------------------------
#define BK        32
#define LDPAD     36                       // 32 + 4 pad (floats)
#define TILE_F    (128 * LDPAD)            // floats per operand tile
#define GEMM_SMEM_BYTES (4 * TILE_F * 4)   // A0,B0,A1,B1

__global__ void __launch_bounds__(256, 1)
tc_gemm(const float* __restrict__ A, const float* __restrict__ Bt,
        const float* __restrict__ R, float* __restrict__ C,
        int M, int N, int K, int epi) {
    extern __shared__ float sm[];
    float* Abuf[2] = { sm,              sm + 2 * TILE_F };
    float* Bbuf[2] = { sm + TILE_F,     sm + 3 * TILE_F };

    const int tid    = threadIdx.x;
    const int wid    = tid >> 5;
    const int lane   = tid & 31;
    const int warp_m = wid & 3;            // 4 bands of 32 rows
    const int warp_n = wid >> 2;           // 2 bands of 64 cols
    const int m0 = blockIdx.y << 7;
    const int n0 = blockIdx.x << 7;

    const int lrow = tid >> 3;             // 0..31? no: 256/8 = 32 -> rows 0..31
    // each thread loads 4 rows spaced 32 apart, 16B per row chunk
    const int lcol = (tid & 7) << 2;       // 0,4,...,28

    const float* Ag = A  + (long)(m0 + lrow) * K + lcol;
    const float* Bg = Bt + (long)(n0 + lrow) * K + lcol;

    float acc[2][8][4];
    #pragma unroll
    for (int i = 0; i < 2; i++)
        #pragma unroll
        for (int j = 0; j < 8; j++)
            #pragma unroll
            for (int q = 0; q < 4; q++) acc[i][j][q] = 0.f;

    const int NC = K / BK;

    float4 av[4], bv[4];

    // prefetch chunk 0
    #pragma unroll
    for (int u = 0; u < 4; u++) {
        av[u] = *reinterpret_cast<const float4*>(Ag + (long)(u * 32) * K);
        bv[u] = *reinterpret_cast<const float4*>(Bg + (long)(u * 32) * K);
    }

    // store chunk 0
    #pragma unroll
    for (int u = 0; u < 4; u++) {
        const int r = lrow + u * 32;
        uint32_t* pa = reinterpret_cast<uint32_t*>(&Abuf[0][r * LDPAD + lcol]);
        uint32_t* pb = reinterpret_cast<uint32_t*>(&Bbuf[0][r * LDPAD + lcol]);
        pa[0] = f2tf32(av[u].x); pa[1] = f2tf32(av[u].y);
        pa[2] = f2tf32(av[u].z); pa[3] = f2tf32(av[u].w);
        pb[0] = f2tf32(bv[u].x); pb[1] = f2tf32(bv[u].y);
        pb[2] = f2tf32(bv[u].z); pb[3] = f2tf32(bv[u].w);
    }
    __syncthreads();

    for (int i = 0; i < NC; i++) {
        const int cur = i & 1;
        // prefetch next chunk (global -> registers)
        if (i + 1 < NC) {
            const long ko = (long)(i + 1) * BK;
            #pragma unroll
            for (int u = 0; u < 4; u++) {
                av[u] = *reinterpret_cast<const float4*>(Ag + (long)(u * 32) * K + ko);
                bv[u] = *reinterpret_cast<const float4*>(Bg + (long)(u * 32) * K + ko);
            }
        }

        // compute on current buffer
        const uint32_t* As = reinterpret_cast<const uint32_t*>(Abuf[cur]);
        const uint32_t* Bs = reinterpret_cast<const uint32_t*>(Bbuf[cur]);
        const int gr = lane >> 2;          // 0..7
        const int gc = lane & 3;           // 0..3

        #pragma unroll
        for (int ks = 0; ks < 4; ks++) {
            const int k0 = ks * 8 + gc;
            uint32_t afrag[2][4], bfrag[8][2];
            #pragma unroll
            for (int mt = 0; mt < 2; mt++) {
                const int r = warp_m * 32 + mt * 16 + gr;
                afrag[mt][0] = As[r * LDPAD + k0];
                afrag[mt][1] = As[(r + 8) * LDPAD + k0];
                afrag[mt][2] = As[r * LDPAD + k0 + 4];
                afrag[mt][3] = As[(r + 8) * LDPAD + k0 + 4];
            }
            #pragma unroll
            for (int nt = 0; nt < 8; nt++) {
                const int n = warp_n * 64 + nt * 8 + gr;
                bfrag[nt][0] = Bs[n * LDPAD + k0];
                bfrag[nt][1] = Bs[n * LDPAD + k0 + 4];
            }
            #pragma unroll
            for (int mt = 0; mt < 2; mt++)
                #pragma unroll
                for (int nt = 0; nt < 8; nt++)
                    mma_tf32(acc[mt][nt], afrag[mt], bfrag[nt]);
        }

        // stage next chunk into the other buffer
        if (i + 1 < NC) {
            const int nxt = cur ^ 1;
            #pragma unroll
            for (int u = 0; u < 4; u++) {
                const int r = lrow + u * 32;
                uint32_t* pa = reinterpret_cast<uint32_t*>(&Abuf[nxt][r * LDPAD + lcol]);
                uint32_t* pb = reinterpret_cast<uint32_t*>(&Bbuf[nxt][r * LDPAD + lcol]);
                pa[0] = f2tf32(av[u].x); pa[1] = f2tf32(av[u].y);
                pa[2] = f2tf32(av[u].z); pa[3] = f2tf32(av[u].w);
                pb[0] = f2tf32(bv[u].x); pb[1] = f2tf32(bv[u].y);
                pb[2] = f2tf32(bv[u].z); pb[3] = f2tf32(bv[u].w);
            }
        }
        __syncthreads();
    }

    // epilogue: acc -> C (+R). c0,c1: row g, cols 2c,2c+1; c2,c3: row g+8.
    const int gr = lane >> 2;
    const int gc = lane & 3;
    #pragma unroll
    for (int mt = 0; mt < 2; mt++) {
        #pragma unroll
        for (int nt = 0; nt < 8; nt++) {
            const int row = m0 + warp_m * 32 + mt * 16 + gr;
            const int col = n0 + warp_n * 64 + nt * 8 + gc * 2;
            float2 lo = make_float2(acc[mt][nt][0], acc[mt][nt][1]);
            float2 hi = make_float2(acc[mt][nt][2], acc[mt][nt][3]);
            if (epi) {
                float2 r0 = *reinterpret_cast<const float2*>(R + (long)row * N + col);
                float2 r1 = *reinterpret_cast<const float2*>(R + (long)(row + 8) * N + col);
                lo.x += r0.x; lo.y += r0.y;
                hi.x += r1.x; hi.y += r1.y;
            }
            *reinterpret_cast<float2*>(C + (long)row * N + col) = lo;
            *reinterpret_cast<float2*>(C + (long)(row + 8) * N + col) = hi;
        }
    }
}

// ---------------------------------------------------------------------------
// Transpose: in [R,C] -> out [C,R]; R,C multiples of 32; block (32,8)
// ---------------------------------------------------------------------------
__global__ void transpose_kernel(const float* __restrict__ in,
                                 float* __restrict__ out, int R, int C) {
    __shared__ float t[32][33];
    const int c0 = blockIdx.x << 5, r0 = blockIdx.y << 5;
    #pragma unroll
    for (int dy = 0; dy < 32; dy += 8) {
        t[threadIdx.y + dy][threadIdx.x] =
            in[(long)(r0 + threadIdx.y + dy) * C + c0 + threadIdx.x];
    }
    __syncthreads();
    #pragma unroll
    for (int dy = 0; dy < 32; dy += 8) {
        out[(long)(c0 + threadIdx.y + dy) * R + r0 + threadIdx.x] =
            t[threadIdx.x][threadIdx.y + dy];
    }
}

// ---------------------------------------------------------------------------
// RMSNorm: one block per row (1024 elements), 256 threads
// ---------------------------------------------------------------------------
__global__ void rmsnorm_kernel(const float* __restrict__ x,
                               const float* __restrict__ g,
                               float* __restrict__ out) {
    const int row = blockIdx.x;
    const int tid = threadIdx.x;
    const float* xr = x + (long)row * D_MODEL;
    float4 v = *reinterpret_cast<const float4*>(xr + tid * 4);
    float s = v.x * v.x + v.y * v.y + v.z * v.z + v.w * v.w;

    #pragma unroll
    for (int off = 16; off > 0; off >>= 1)
        s += __shfl_xor_sync(0xffffffffu, s, off);

    __shared__ float red[8];
    if ((tid & 31) == 0) red[tid >> 5] = s;
    __syncthreads();
    float total;
    {
        float t = (tid < 8) ? red[tid] : 0.f;
        #pragma unroll
        for (int off = 4; off > 0; off >>= 1)
            t += __shfl_xor_sync(0xffffffffu, t, off);
        __shared__ float bc;
        if (tid == 0) bc = t;
        __syncthreads();
        total = bc;
    }
    float inv = rsqrtf(total * (1.0f / D_MODEL) + 1e-6f);
    float4 gv = *reinterpret_cast<const float4*>(g + tid * 4);
    float4 o;
    o.x = v.x * inv * gv.x;
    o.y = v.y * inv * gv.y;
    o.z = v.z * inv * gv.z;
    o.w = v.w * inv * gv.w;
    *reinterpret_cast<float4*>(out + (long)row * D_MODEL + tid * 4) = o;
}

// ---------------------------------------------------------------------------
// RoPE (half-split, in place)
// ---------------------------------------------------------------------------
__global__ void rope_kernel(float* __restrict__ q, float* __restrict__ k) {
    const int row = blockIdx.x;
    const int t = row & (SEQ - 1);
    const int tid = threadIdx.x;

    float* ptr;
    int j;
    if (tid < 512) {
        int h = tid >> 5; j = tid & 31;
        ptr = q + (long)row * D_MODEL + h * HEAD_DIM;
    } else {
        int u = tid - 512;
        int h = u >> 5; j = u & 31;
        ptr = k + (long)row * (N_KV * HEAD_DIM) + h * HEAD_DIM;
    }
    float inv = (float)exp(-(double)j / 32.0 * 9.210340371976184);
    float fr = (float)t * inv;
    float c = cosf(fr), s = sinf(fr);
    float x1 = ptr[j], x2 = ptr[j + 32];
    ptr[j]      = x1 * c - x2 * s;
    ptr[j + 32] = x2 * c + x1 * s;
}

// ---------------------------------------------------------------------------
// Flash-style causal attention, GQA
// ---------------------------------------------------------------------------
__global__ void __launch_bounds__(128)
attn_kernel(const float* __restrict__ q, const float* __restrict__ k,
            const float* __restrict__ v, float* __restrict__ o) {
    __shared__ float Ks[64 * 65];
    __shared__ float Vs[64 * 65];

    const int tid = threadIdx.x;
    const int t0  = blockIdx.x * 128;
    const int bh  = blockIdx.y;
    const int b   = bh >> 4;
    const int hq  = bh & 15;
    const int kvh = hq >> 1;
    const int t   = t0 + tid;

    float qreg[64];
    {
        const float* qp = q + (long)(b * SEQ + t) * D_MODEL + hq * HEAD_DIM;
        #pragma unroll
        for (int d4 = 0; d4 < 16; d4++) {
            float4 vq = *reinterpret_cast<const float4*>(qp + d4 * 4);
            qreg[d4 * 4 + 0] = vq.x * 0.125f;
            qreg[d4 * 4 + 1] = vq.y * 0.125f;
            qreg[d4 * 4 + 2] = vq.z * 0.125f;
            qreg[d4 * 4 + 3] = vq.w * 0.125f;
        }
    }

    float acc[64];
    #pragma unroll
    for (int d = 0; d < 64; d++) acc[d] = 0.f;
    float m = -1e30f, l = 0.f;
    float sc[64];

    const int ntiles = (t0 >> 6) + 2;
    for (int it = 0; it < ntiles; it++) {
        const int s0 = it * 64;
        __syncthreads();
        for (int i = tid; i < 64 * 64; i += 128) {
            int r = i >> 6, d = i & 63;
            long base = (long)(b * SEQ + s0 + r) * (N_KV * HEAD_DIM) + kvh * HEAD_DIM + d;
            Ks[r * 65 + d] = k[base];
            Vs[r * 65 + d] = v[base];
        }
        __syncthreads();

        float tmax = -1e30f;
        for (int j = 0; j < 64; j++) {
            float s = 0.f;
            const float* kr = &Ks[j * 65];
            #pragma unroll
            for (int d = 0; d < 64; d++) s += qreg[d] * kr[d];
            s = (s0 + j <= t) ? s : -1e30f;
            sc[j] = s;
            tmax = fmaxf(tmax, s);
        }

        float mnew = fmaxf(m, tmax);
        float corr = expf(m - mnew);
        l *= corr;
        #pragma unroll
        for (int d = 0; d < 64; d++) acc[d] *= corr;

        for (int j = 0; j < 64; j++) {
            float p = expf(sc[j] - mnew);
            l += p;
            const float* vr = &Vs[j * 65];
            #pragma unroll
            for (int d = 0; d < 64; d++) acc[d] += p * vr[d];
        }
        m = mnew;
    }

    const float invl = 1.0f / l;
    float* op = o + (long)(b * SEQ + t) * D_MODEL + hq * HEAD_DIM;
    #pragma unroll
    for (int d4 = 0; d4 < 16; d4++) {
        float4 ov;
        ov.x = acc[d4 * 4 + 0] * invl;
        ov.y = acc[d4 * 4 + 1] * invl;
        ov.z = acc[d4 * 4 + 2] * invl;
        ov.w = acc[d4 * 4 + 3] * invl;
        *reinterpret_cast<float4*>(op + d4 * 4) = ov;
    }
}

// ---------------------------------------------------------------------------
// SiLU(a) * b -> a  (in place)
// ---------------------------------------------------------------------------
__global__ void silu_mul_kernel(float* __restrict__ a,
                                const float* __restrict__ b, long n) {
    long i = (long)blockIdx.x * blockDim.x + threadIdx.x;
    long stride = (long)gridDim.x * blockDim.x;
    for (; i < n; i += stride) {
        float x = a[i];
        float s = x / (1.0f + expf(-x));
        a[i] = s * b[i];
    }
}

// ---------------------------------------------------------------------------
// Launch
// ---------------------------------------------------------------------------
extern "C" void kernel_launch(void* const* d_in, const int* in_sizes, int n_in,
                              void* d_out, int out_size) {
    const float* x  = (const float*)d_in[0];
    const float* g1 = (const float*)d_in[1];
    const float* g2 = (const float*)d_in[2];
    const float* wq = (const float*)d_in[3];
    const float* wk = (const float*)d_in[4];
    const float* wv = (const float*)d_in[5];
    const float* wo = (const float*)d_in[6];
    const float* w1 = (const float*)d_in[7];
    const float* w2 = (const float*)d_in[8];
    const float* w3 = (const float*)d_in[9];
    float* out = (float*)d_out;

    float *h, *q, *k, *v, *ao, *h2, *a, *bb;
    float *wqT, *wkT, *wvT, *woT, *w1T, *w2T, *w3T;
    cudaGetSymbolAddress((void**)&h,  g_h);
    cudaGetSymbolAddress((void**)&q,  g_q);
    cudaGetSymbolAddress((void**)&k,  g_k);
    cudaGetSymbolAddress((void**)&v,  g_v);
    cudaGetSymbolAddress((void**)&ao, g_ao);
    cudaGetSymbolAddress((void**)&h2, g_h2);
    cudaGetSymbolAddress((void**)&a,  g_a);
    cudaGetSymbolAddress((void**)&bb, g_b);
    cudaGetSymbolAddress((void**)&wqT, g_wqT);
    cudaGetSymbolAddress((void**)&wkT, g_wkT);
    cudaGetSymbolAddress((void**)&wvT, g_wvT);
    cudaGetSymbolAddress((void**)&woT, g_woT);
    cudaGetSymbolAddress((void**)&w1T, g_w1T);
    cudaGetSymbolAddress((void**)&w2T, g_w2T);
    cudaGetSymbolAddress((void**)&w3T, g_w3T);

    cudaFuncSetAttribute(tc_gemm, cudaFuncAttributeMaxDynamicSharedMemorySize,
                         GEMM_SMEM_BYTES);

    dim3 tb(32, 8);
    transpose_kernel<<<dim3(D_MODEL / 32, D_MODEL / 32), tb>>>(wq, wqT, D_MODEL, D_MODEL);
    transpose_kernel<<<dim3((N_KV * HEAD_DIM) / 32, D_MODEL / 32), tb>>>(wk, wkT, D_MODEL, N_KV * HEAD_DIM);
    transpose_kernel<<<dim3((N_KV * HEAD_DIM) / 32, D_MODEL / 32), tb>>>(wv, wvT, D_MODEL, N_KV * HEAD_DIM);
    transpose_kernel<<<dim3(D_MODEL / 32, D_MODEL / 32), tb>>>(wo, woT, D_MODEL, D_MODEL);
    transpose_kernel<<<dim3(HIDDEN / 32, D_MODEL / 32), tb>>>(w1, w1T, D_MODEL, HIDDEN);
    transpose_kernel<<<dim3(HIDDEN / 32, D_MODEL / 32), tb>>>(w2, w2T, D_MODEL, HIDDEN);
    transpose_kernel<<<dim3(D_MODEL / 32, HIDDEN / 32), tb>>>(w3, w3T, HIDDEN, D_MODEL);

    // 1. h = rmsnorm(x, g1)
    rmsnorm_kernel<<<BT, 256>>>(x, g1, h);

    // 2. q/k/v projections (tensor core tf32)
    tc_gemm<<<dim3(D_MODEL / 128, BT / 128), 256, GEMM_SMEM_BYTES>>>(h, wqT, nullptr, q, BT, D_MODEL, D_MODEL, 0);
    tc_gemm<<<dim3((N_KV * HEAD_DIM) / 128, BT / 128), 256, GEMM_SMEM_BYTES>>>(h, wkT, nullptr, k, BT, N_KV * HEAD_DIM, D_MODEL, 0);
    tc_gemm<<<dim3((N_KV * HEAD_DIM) / 128, BT / 128), 256, GEMM_SMEM_BYTES>>>(h, wvT, nullptr, v, BT, N_KV * HEAD_DIM, D_MODEL, 0);

    // 3. RoPE in place
    rope_kernel<<<BT, 768>>>(q, k);

    // 4. causal GQA attention
    attn_kernel<<<dim3(SEQ / 128, BATCH * N_HEADS), 128>>>(q, k, v, ao);

    // 5. out-proj + residual: d_out = ao @ wo + x
    tc_gemm<<<dim3(D_MODEL / 128, BT / 128), 256, GEMM_SMEM_BYTES>>>(ao, woT, x, out, BT, D_MODEL, D_MODEL, 1);

    // 6. h2 = rmsnorm(d_out, g2)
    rmsnorm_kernel<<<BT, 256>>>(out, g2, h2);

    // 7. FFN branches
    tc_gemm<<<dim3(HIDDEN / 128, BT / 128), 256, GEMM_SMEM_BYTES>>>(h2, w1T, nullptr, a,  BT, HIDDEN, D_MODEL, 0);
    tc_gemm<<<dim3(HIDDEN / 128, BT / 128), 256, GEMM_SMEM_BYTES>>>(h2, w2T, nullptr, bb, BT, HIDDEN, D_MODEL, 0);

    // 8. a = silu(a) * b
    silu_mul_kernel<<<2048, 256>>>(a, bb, (long)BT * HIDDEN);

    // 9. d_out += a @ w3
    tc_gemm<<<dim3(D_MODEL / 128, BT / 128), 256, GEMM_SMEM_BYTES>>>(a, w3T, out, out, BT, D_MODEL, HIDDEN, 1);
}

// round 4
// speedup vs baseline: 2.8101x; 1.7427x over previous
#include <cuda_runtime.h>
#include <cuda_bf16.h>
#include <math.h>
#include <stdint.h>

// ---------------------------------------------------------------------------
// Problem constants
// ---------------------------------------------------------------------------
#define D_MODEL   1024
#define N_HEADS   16
#define N_KV      8
#define HEAD_DIM  64
#define HIDDEN    4096
#define BATCH     4
#define SEQ       2048
#define BT        (BATCH * SEQ)        // 8192 rows

// ---------------------------------------------------------------------------
// Scratch (device globals: allocation-free rule)
// ---------------------------------------------------------------------------
__device__ float g_h  [BT * D_MODEL];
__device__ float g_q  [BT * D_MODEL];
__device__ float g_k  [BT * N_KV * HEAD_DIM];
__device__ float g_v  [BT * N_KV * HEAD_DIM];
__device__ float g_ao [BT * D_MODEL];
__device__ float g_h2 [BT * D_MODEL];
__device__ float g_a  [BT * HIDDEN];
__device__ float g_b  [BT * HIDDEN];

// transposed weights [N,K] (K contiguous) so B is K-major (col-major for mma)
__device__ float g_wqT[D_MODEL * D_MODEL];
__device__ float g_wkT[(N_KV * HEAD_DIM) * D_MODEL];
__device__ float g_wvT[(N_KV * HEAD_DIM) * D_MODEL];
__device__ float g_woT[D_MODEL * D_MODEL];
__device__ float g_w1T[HIDDEN * D_MODEL];
__device__ float g_w2T[HIDDEN * D_MODEL];
__device__ float g_w3T[D_MODEL * HIDDEN];

// ---------------------------------------------------------------------------
// Helpers
// ---------------------------------------------------------------------------
__device__ __forceinline__ uint32_t f2tf32(float x) {
    uint32_t r;
    asm("cvt.rna.tf32.f32 %0, %1;" : "=r"(r) : "f"(x));
    return r;
}

__device__ __forceinline__ void mma_tf32(float* c, const uint32_t* a, const uint32_t* b) {
    asm volatile(
        "mma.sync.aligned.m16n8k8.row.col.f32.tf32.tf32.f32 "
        "{%0,%1,%2,%3}, {%4,%5,%6,%7}, {%8,%9}, {%0,%1,%2,%3};\n"
        : "+f"(c[0]), "+f"(c[1]), "+f"(c[2]), "+f"(c[3])
        : "r"(a[0]), "r"(a[1]), "r"(a[2]), "r"(a[3]), "r"(b[0]), "r"(b[1]));
}

// ---------------------------------------------------------------------------
// tf32 tensor-core GEMM (unchanged from R3, passing)
// ---------------------------------------------------------------------------
#define BK        32
#define LDPAD     36
#define TILE_F    (128 * LDPAD)
#define GEMM_SMEM_BYTES (4 * TILE_F * 4)

__global__ void __launch_bounds__(256, 1)
tc_gemm(const float* __restrict__ A, const float* __restrict__ Bt,
        const float* __restrict__ R, float* __restrict__ C,
        int M, int N, int K, int epi) {
    extern __shared__ float sm[];
    float* Abuf[2] = { sm,              sm + 2 * TILE_F };
    float* Bbuf[2] = { sm + TILE_F,     sm + 3 * TILE_F };

    const int tid    = threadIdx.x;
    const int wid    = tid >> 5;
    const int lane   = tid & 31;
    const int warp_m = wid & 3;
    const int warp_n = wid >> 2;
    const int m0 = blockIdx.y << 7;
    const int n0 = blockIdx.x << 7;

    const int lrow = tid >> 3;
    const int lcol = (tid & 7) << 2;

    const float* Ag = A  + (long)(m0 + lrow) * K + lcol;
    const float* Bg = Bt + (long)(n0 + lrow) * K + lcol;

    float acc[2][8][4];
    #pragma unroll
    for (int i = 0; i < 2; i++)
        #pragma unroll
        for (int j = 0; j < 8; j++)
            #pragma unroll
            for (int q = 0; q < 4; q++) acc[i][j][q] = 0.f;

    const int NC = K / BK;
    float4 av[4], bv[4];

    #pragma unroll
    for (int u = 0; u < 4; u++) {
        av[u] = *reinterpret_cast<const float4*>(Ag + (long)(u * 32) * K);
        bv[u] = *reinterpret_cast<const float4*>(Bg + (long)(u * 32) * K);
    }
    #pragma unroll
    for (int u = 0; u < 4; u++) {
        const int r = lrow + u * 32;
        uint32_t* pa = reinterpret_cast<uint32_t*>(&Abuf[0][r * LDPAD + lcol]);
        uint32_t* pb = reinterpret_cast<uint32_t*>(&Bbuf[0][r * LDPAD + lcol]);
        pa[0] = f2tf32(av[u].x); pa[1] = f2tf32(av[u].y);
        pa[2] = f2tf32(av[u].z); pa[3] = f2tf32(av[u].w);
        pb[0] = f2tf32(bv[u].x); pb[1] = f2tf32(bv[u].y);
        pb[2] = f2tf32(bv[u].z); pb[3] = f2tf32(bv[u].w);
    }
    __syncthreads();

    for (int i = 0; i < NC; i++) {
        const int cur = i & 1;
        if (i + 1 < NC) {
            const long ko = (long)(i + 1) * BK;
            #pragma unroll
            for (int u = 0; u < 4; u++) {
                av[u] = *reinterpret_cast<const float4*>(Ag + (long)(u * 32) * K + ko);
                bv[u] = *reinterpret_cast<const float4*>(Bg + (long)(u * 32) * K + ko);
            }
        }

        const uint32_t* As = reinterpret_cast<const uint32_t*>(Abuf[cur]);
        const uint32_t* Bs = reinterpret_cast<const uint32_t*>(Bbuf[cur]);
        const int gr = lane >> 2;
        const int gc = lane & 3;

        #pragma unroll
        for (int ks = 0; ks < 4; ks++) {
            const int k0 = ks * 8 + gc;
            uint32_t afrag[2][4], bfrag[8][2];
            #pragma unroll
            for (int mt = 0; mt < 2; mt++) {
                const int r = warp_m * 32 + mt * 16 + gr;
                afrag[mt][0] = As[r * LDPAD + k0];
                afrag[mt][1] = As[(r + 8) * LDPAD + k0];
                afrag[mt][2] = As[r * LDPAD + k0 + 4];
                afrag[mt][3] = As[(r + 8) * LDPAD + k0 + 4];
            }
            #pragma unroll
            for (int nt = 0; nt < 8; nt++) {
                const int n = warp_n * 64 + nt * 8 + gr;
                bfrag[nt][0] = Bs[n * LDPAD + k0];
                bfrag[nt][1] = Bs[n * LDPAD + k0 + 4];
            }
            #pragma unroll
            for (int mt = 0; mt < 2; mt++)
                #pragma unroll
                for (int nt = 0; nt < 8; nt++)
                    mma_tf32(acc[mt][nt], afrag[mt], bfrag[nt]);
        }

        if (i + 1 < NC) {
            const int nxt = cur ^ 1;
            #pragma unroll
            for (int u = 0; u < 4; u++) {
                const int r = lrow + u * 32;
                uint32_t* pa = reinterpret_cast<uint32_t*>(&Abuf[nxt][r * LDPAD + lcol]);
                uint32_t* pb = reinterpret_cast<uint32_t*>(&Bbuf[nxt][r * LDPAD + lcol]);
                pa[0] = f2tf32(av[u].x); pa[1] = f2tf32(av[u].y);
                pa[2] = f2tf32(av[u].z); pa[3] = f2tf32(av[u].w);
                pb[0] = f2tf32(bv[u].x); pb[1] = f2tf32(bv[u].y);
                pb[2] = f2tf32(bv[u].z); pb[3] = f2tf32(bv[u].w);
            }
        }
        __syncthreads();
    }

    const int gr = lane >> 2;
    const int gc = lane & 3;
    #pragma unroll
    for (int mt = 0; mt < 2; mt++) {
        #pragma unroll
        for (int nt = 0; nt < 8; nt++) {
            const int row = m0 + warp_m * 32 + mt * 16 + gr;
            const int col = n0 + warp_n * 64 + nt * 8 + gc * 2;
            float2 lo = make_float2(acc[mt][nt][0], acc[mt][nt][1]);
            float2 hi = make_float2(acc[mt][nt][2], acc[mt][nt][3]);
            if (epi) {
                float2 r0 = *reinterpret_cast<const float2*>(R + (long)row * N + col);
                float2 r1 = *reinterpret_cast<const float2*>(R + (long)(row + 8) * N + col);
                lo.x += r0.x; lo.y += r0.y;
                hi.x += r1.x; hi.y += r1.y;
            }
            *reinterpret_cast<float2*>(C + (long)row * N + col) = lo;
            *reinterpret_cast<float2*>(C + (long)(row + 8) * N + col) = hi;
        }
    }
}

// ---------------------------------------------------------------------------
// Tensor-core flash attention (tf32 mma), causal GQA.
// CTA: 128 threads (4 warps), 128 Q rows per CTA, warp = 32 rows.
// Q in smem (stride 68), K tiles (stride 68), V tiles (stride 72), all tf32.
// S = Q@K^T via mma; online softmax in C-fragments; P->A frags via shuffles;
// O += P@V via mma.
// ---------------------------------------------------------------------------
#define QS_LD 68
#define KS_LD 68
#define VS_LD 72
#define ATTN_SMEM ((128 * QS_LD + 64 * KS_LD + 64 * VS_LD) * 4)

__global__ void __launch_bounds__(128)
attn_mma(const float* __restrict__ q, const float* __restrict__ k,
         const float* __restrict__ v, float* __restrict__ o) {
    extern __shared__ uint32_t smu[];
    uint32_t* Qs = smu;
    uint32_t* Ks = smu + 128 * QS_LD;
    uint32_t* Vs = Ks + 64 * KS_LD;

    const int tid  = threadIdx.x;
    const int warp = tid >> 5;
    const int lane = tid & 31;
    const int gr = lane >> 2;
    const int gc = lane & 3;
    const int wr = warp << 5;              // warp row offset within tile (0..96)

    const int t0  = blockIdx.x << 7;
    const int bh  = blockIdx.y;
    const int b   = bh >> 4;
    const int hq  = bh & 15;
    const int kvh = hq >> 1;

    // Load Q tile (128 rows x 64 dims), scaled 1/8, tf32
    for (int i = tid; i < 128 * 16; i += 128) {
        const int row = i >> 4;
        const int c4 = (i & 15) << 2;
        float4 vq = *reinterpret_cast<const float4*>(
            q + (long)(b * SEQ + t0 + row) * D_MODEL + hq * HEAD_DIM + c4);
        uint32_t* p = &Qs[row * QS_LD + c4];
        p[0] = f2tf32(vq.x * 0.125f);
        p[1] = f2tf32(vq.y * 0.125f);
        p[2] = f2tf32(vq.z * 0.125f);
        p[3] = f2tf32(vq.w * 0.125f);
    }

    float ofrag[2][8][4];
    #pragma unroll
    for (int mt = 0; mt < 2; mt++)
        #pragma unroll
        for (int nt = 0; nt < 8; nt++)
            #pragma unroll
            for (int r = 0; r < 4; r++) ofrag[mt][nt][r] = 0.f;

    float mrow[2][2] = {{-1e30f, -1e30f}, {-1e30f, -1e30f}};
    float lrow[2][2] = {{0.f, 0.f}, {0.f, 0.f}};

    const int ntiles = (t0 >> 6) + 2;
    for (int it = 0; it < ntiles; it++) {
        const int s0 = it << 6;
        __syncthreads();
        // load K,V tiles (64 keys x 64 dims), tf32
        for (int i = tid; i < 64 * 16; i += 128) {
            const int row = i >> 4;
            const int c4 = (i & 15) << 2;
            const long base = (long)(b * SEQ + s0 + row) * (N_KV * HEAD_DIM) + kvh * HEAD_DIM + c4;
            float4 kv4 = *reinterpret_cast<const float4*>(k + base);
            float4 vv4 = *reinterpret_cast<const float4*>(v + base);
            uint32_t* pk = &Ks[row * KS_LD + c4];
            pk[0] = f2tf32(kv4.x); pk[1] = f2tf32(kv4.y);
            pk[2] = f2tf32(kv4.z); pk[3] = f2tf32(kv4.w);
            uint32_t* pv = &Vs[row * VS_LD + c4];
            pv[0] = f2tf32(vv4.x); pv[1] = f2tf32(vv4.y);
            pv[2] = f2tf32(vv4.z); pv[3] = f2tf32(vv4.w);
        }
        __syncthreads();

        // ---- S = Q @ K^T ----
        float sfrag[2][8][4];
        #pragma unroll
        for (int mt = 0; mt < 2; mt++)
            #pragma unroll
            for (int nt = 0; nt < 8; nt++)
                #pragma unroll
                for (int r = 0; r < 4; r++) sfrag[mt][nt][r] = 0.f;

        #pragma unroll
        for (int ks = 0; ks < 8; ks++) {
            const int k0 = ks * 8 + gc;
            uint32_t aq[2][4];
            #pragma unroll
            for (int mt = 0; mt < 2; mt++) {
                const int r = wr + mt * 16 + gr;
                aq[mt][0] = Qs[r * QS_LD + k0];
                aq[mt][1] = Qs[(r + 8) * QS_LD + k0];
                aq[mt][2] = Qs[r * QS_LD + k0 + 4];
                aq[mt][3] = Qs[(r + 8) * QS_LD + k0 + 4];
            }
            #pragma unroll
            for (int nt = 0; nt < 8; nt++) {
                uint32_t bk[2];
                bk[0] = Ks[(nt * 8 + gr) * KS_LD + k0];
                bk[1] = Ks[(nt * 8 + gr) * KS_LD + k0 + 4];
                mma_tf32(sfrag[0][nt], aq[0], bk);
                mma_tf32(sfrag[1][nt], aq[1], bk);
            }
        }

        // ---- causal mask (only diagonal tiles) ----
        if (it >= ntiles - 2) {
            #pragma unroll
            for (int mt = 0; mt < 2; mt++) {
                const int rA = t0 + wr + mt * 16 + gr;
                const int rB = rA + 8;
                #pragma unroll
                for (int nt = 0; nt < 8; nt++) {
                    const int cb = s0 + nt * 8 + 2 * gc;
                    if (cb     > rA) sfrag[mt][nt][0] = -1e30f;
                    if (cb + 1 > rA) sfrag[mt][nt][1] = -1e30f;
                    if (cb     > rB) sfrag[mt][nt][2] = -1e30f;
                    if (cb + 1 > rB) sfrag[mt][nt][3] = -1e30f;
                }
            }
        }

        // ---- online softmax ----
        #pragma unroll
        for (int mt = 0; mt < 2; mt++) {
            float r0 = -1e30f, r1 = -1e30f;
            #pragma unroll
            for (int nt = 0; nt < 8; nt++) {
                r0 = fmaxf(r0, fmaxf(sfrag[mt][nt][0], sfrag[mt][nt][1]));
                r1 = fmaxf(r1, fmaxf(sfrag[mt][nt][2], sfrag[mt][nt][3]));
            }
            r0 = fmaxf(r0, __shfl_xor_sync(0xffffffffu, r0, 1));
            r0 = fmaxf(r0, __shfl_xor_sync(0xffffffffu, r0, 2));
            r1 = fmaxf(r1, __shfl_xor_sync(0xffffffffu, r1, 1));
            r1 = fmaxf(r1, __shfl_xor_sync(0xffffffffu, r1, 2));

            const float mn0 = fmaxf(mrow[mt][0], r0);
            const float mn1 = fmaxf(mrow[mt][1], r1);
            const float c0 = __expf(mrow[mt][0] - mn0);
            const float c1 = __expf(mrow[mt][1] - mn1);
            lrow[mt][0] *= c0;
            lrow[mt][1] *= c1;
            #pragma unroll
            for (int nt = 0; nt < 8; nt++) {
                ofrag[mt][nt][0] *= c0; ofrag[mt][nt][1] *= c0;
                ofrag[mt][nt][2] *= c1; ofrag[mt][nt][3] *= c1;
            }
            float s0s = 0.f, s1s = 0.f;
            #pragma unroll
            for (int nt = 0; nt < 8; nt++) {
                sfrag[mt][nt][0] = __expf(sfrag[mt][nt][0] - mn0);
                sfrag[mt][nt][1] = __expf(sfrag[mt][nt][1] - mn0);
                sfrag[mt][nt][2] = __expf(sfrag[mt][nt][2] - mn1);
                sfrag[mt][nt][3] = __expf(sfrag[mt][nt][3] - mn1);
                s0s += sfrag[mt][nt][0] + sfrag[mt][nt][1];
                s1s += sfrag[mt][nt][2] + sfrag[mt][nt][3];
            }
            s0s += __shfl_xor_sync(0xffffffffu, s0s, 1);
            s0s += __shfl_xor_sync(0xffffffffu, s0s, 2);
            s1s += __shfl_xor_sync(0xffffffffu, s1s, 1);
            s1s += __shfl_xor_sync(0xffffffffu, s1s, 2);
            lrow[mt][0] += s0s;
            lrow[mt][1] += s1s;
            mrow[mt][0] = mn0;
            mrow[mt][1] = mn1;
        }

        // ---- O += P @ V ----
        const int srcA = (gr << 2) | (gc >> 1);
        const bool odd = gc & 1;
        #pragma unroll
        for (int ks = 0; ks < 8; ks++) {
            uint32_t ap[2][4];
            #pragma unroll
            for (int mt = 0; mt < 2; mt++) {
                const float p0 = sfrag[mt][ks][0], p1 = sfrag[mt][ks][1];
                const float p2 = sfrag[mt][ks][2], p3 = sfrag[mt][ks][3];
                const float v00 = __shfl_sync(0xffffffffu, p0, srcA);
                const float v01 = __shfl_sync(0xffffffffu, p1, srcA);
                const float v10 = __shfl_sync(0xffffffffu, p0, srcA + 2);
                const float v11 = __shfl_sync(0xffffffffu, p1, srcA + 2);
                const float w00 = __shfl_sync(0xffffffffu, p2, srcA);
                const float w01 = __shfl_sync(0xffffffffu, p3, srcA);
                const float w10 = __shfl_sync(0xffffffffu, p2, srcA + 2);
                const float w11 = __shfl_sync(0xffffffffu, p3, srcA + 2);
                ap[mt][0] = f2tf32(odd ? v01 : v00);
                ap[mt][1] = f2tf32(odd ? w01 : w00);
                ap[mt][2] = f2tf32(odd ? v11 : v10);
                ap[mt][3] = f2tf32(odd ? w11 : w10);
            }
            #pragma unroll
            for (int nt = 0; nt < 8; nt++) {
                uint32_t bv2[2];
                bv2[0] = Vs[(ks * 8 + gc) * VS_LD + nt * 8 + gr];
                bv2[1] = Vs[(ks * 8 + gc + 4) * VS_LD + nt * 8 + gr];
                mma_tf32(ofrag[0][nt], ap[0], bv2);
                mma_tf32(ofrag[1][nt], ap[1], bv2);
            }
        }
    }

    // ---- write O / l ----
    #pragma unroll
    for (int mt = 0; mt < 2; mt++) {
        const int rowA = t0 + wr + mt * 16 + gr;
        const int rowB = rowA + 8;
        const float il0 = 1.0f / lrow[mt][0];
        const float il1 = 1.0f / lrow[mt][1];
        #pragma unroll
        for (int nt = 0; nt < 8; nt++) {
            const int col = hq * HEAD_DIM + nt * 8 + 2 * gc;
            float2 lo = make_float2(ofrag[mt][nt][0] * il0, ofrag[mt][nt][1] * il0);
            float2 hi = make_float2(ofrag[mt][nt][2] * il1, ofrag[mt][nt][3] * il1);
            *reinterpret_cast<float2*>(o + (long)(b * SEQ + rowA) * D_MODEL + col) = lo;
            *reinterpret_cast<float2*>(o + (long)(b * SEQ + rowB) * D_MODEL + col) = hi;
        }
    }
}

// ---------------------------------------------------------------------------
// Transpose: in [R,C] -> out [C,R]
// ---------------------------------------------------------------------------
__global__ void transpose_kernel(const float* __restrict__ in,
                                 float* __restrict__ out, int R, int C) {
    __shared__ float t[32][33];
    const int c0 = blockIdx.x << 5, r0 = blockIdx.y << 5;
    #pragma unroll
    for (int dy = 0; dy < 32; dy += 8) {
        t[threadIdx.y + dy][threadIdx.x] =
            in[(long)(r0 + threadIdx.y + dy) * C + c0 + threadIdx.x];
    }
    __syncthreads();
    #pragma unroll
    for (int dy = 0; dy < 32; dy += 8) {
        out[(long)(c0 + threadIdx.y + dy) * R + r0 + threadIdx.x] =
            t[threadIdx.x][threadIdx.y + dy];
    }
}

// ---------------------------------------------------------------------------
// RMSNorm
// ---------------------------------------------------------------------------
__global__ void rmsnorm_kernel(const float* __restrict__ x,
                               const float* __restrict__ g,
                               float* __restrict__ out) {
    const int row = blockIdx.x;
    const int tid = threadIdx.x;
    const float* xr = x + (long)row * D_MODEL;
    float4 v = *reinterpret_cast<const float4*>(xr + tid * 4);
    float s = v.x * v.x + v.y * v.y + v.z * v.z + v.w * v.w;

    #pragma unroll
    for (int off = 16; off > 0; off >>= 1)
        s += __shfl_xor_sync(0xffffffffu, s, off);

    __shared__ float red[8];
    if ((tid & 31) == 0) red[tid >> 5] = s;
    __syncthreads();
    float total;
    {
        float t = (tid < 8) ? red[tid] : 0.f;
        #pragma unroll
        for (int off = 4; off > 0; off >>= 1)
            t += __shfl_xor_sync(0xffffffffu, t, off);
        __shared__ float bc;
        if (tid == 0) bc = t;
        __syncthreads();
        total = bc;
    }
    float inv = rsqrtf(total * (1.0f / D_MODEL) + 1e-6f);
    float4 gv = *reinterpret_cast<const float4*>(g + tid * 4);
    float4 o;
    o.x = v.x * inv * gv.x;
    o.y = v.y * inv * gv.y;
    o.z = v.z * inv * gv.z;
    o.w = v.w * inv * gv.w;
    *reinterpret_cast<float4*>(out + (long)row * D_MODEL + tid * 4) = o;
}

// ---------------------------------------------------------------------------
// RoPE (half-split, in place)
// ---------------------------------------------------------------------------
__global__ void rope_kernel(float* __restrict__ q, float* __restrict__ k) {
    const int row = blockIdx.x;
    const int t = row & (SEQ - 1);
    const int tid = threadIdx.x;

    float* ptr;
    int j;
    if (tid < 512) {
        int h = tid >> 5; j = tid & 31;
        ptr = q + (long)row * D_MODEL + h * HEAD_DIM;
    } else {
        int u = tid - 512;
        int h = u >> 5; j = u & 31;
        ptr = k + (long)row * (N_KV * HEAD_DIM) + h * HEAD_DIM;
    }
    float inv = (float)exp(-(double)j / 32.0 * 9.210340371976184);
    float fr = (float)t * inv;
    float c = cosf(fr), s = sinf(fr);
    float x1 = ptr[j], x2 = ptr[j + 32];
    ptr[j]      = x1 * c - x2 * s;
    ptr[j + 32] = x2 * c + x1 * s;
}

// ---------------------------------------------------------------------------
// SiLU(a) * b -> a  (in place)
// ---------------------------------------------------------------------------
__global__ void silu_mul_kernel(float* __restrict__ a,
                                const float* __restrict__ b, long n) {
    long i = (long)blockIdx.x * blockDim.x + threadIdx.x;
    long stride = (long)gridDim.x * blockDim.x;
    for (; i < n; i += stride) {
        float x = a[i];
        float s = x / (1.0f + expf(-x));
        a[i] = s * b[i];
    }
}

// ---------------------------------------------------------------------------
// Launch
// ---------------------------------------------------------------------------
extern "C" void kernel_launch(void* const* d_in, const int* in_sizes, int n_in,
                              void* d_out, int out_size) {
    const float* x  = (const float*)d_in[0];
    const float* g1 = (const float*)d_in[1];
    const float* g2 = (const float*)d_in[2];
    const float* wq = (const float*)d_in[3];
    const float* wk = (const float*)d_in[4];
    const float* wv = (const float*)d_in[5];
    const float* wo = (const float*)d_in[6];
    const float* w1 = (const float*)d_in[7];
    const float* w2 = (const float*)d_in[8];
    const float* w3 = (const float*)d_in[9];
    float* out = (float*)d_out;

    float *h, *q, *k, *v, *ao, *h2, *a, *bb;
    float *wqT, *wkT, *wvT, *woT, *w1T, *w2T, *w3T;
    cudaGetSymbolAddress((void**)&h,  g_h);
    cudaGetSymbolAddress((void**)&q,  g_q);
    cudaGetSymbolAddress((void**)&k,  g_k);
    cudaGetSymbolAddress((void**)&v,  g_v);
    cudaGetSymbolAddress((void**)&ao, g_ao);
    cudaGetSymbolAddress((void**)&h2, g_h2);
    cudaGetSymbolAddress((void**)&a,  g_a);
    cudaGetSymbolAddress((void**)&bb, g_b);
    cudaGetSymbolAddress((void**)&wqT, g_wqT);
    cudaGetSymbolAddress((void**)&wkT, g_wkT);
    cudaGetSymbolAddress((void**)&wvT, g_wvT);
    cudaGetSymbolAddress((void**)&woT, g_woT);
    cudaGetSymbolAddress((void**)&w1T, g_w1T);
    cudaGetSymbolAddress((void**)&w2T, g_w2T);
    cudaGetSymbolAddress((void**)&w3T, g_w3T);

    cudaFuncSetAttribute(tc_gemm, cudaFuncAttributeMaxDynamicSharedMemorySize,
                         GEMM_SMEM_BYTES);
    cudaFuncSetAttribute(attn_mma, cudaFuncAttributeMaxDynamicSharedMemorySize,
                         ATTN_SMEM);

    dim3 tb(32, 8);
    transpose_kernel<<<dim3(D_MODEL / 32, D_MODEL / 32), tb>>>(wq, wqT, D_MODEL, D_MODEL);
    transpose_kernel<<<dim3((N_KV * HEAD_DIM) / 32, D_MODEL / 32), tb>>>(wk, wkT, D_MODEL, N_KV * HEAD_DIM);
    transpose_kernel<<<dim3((N_KV * HEAD_DIM) / 32, D_MODEL / 32), tb>>>(wv, wvT, D_MODEL, N_KV * HEAD_DIM);
    transpose_kernel<<<dim3(D_MODEL / 32, D_MODEL / 32), tb>>>(wo, woT, D_MODEL, D_MODEL);
    transpose_kernel<<<dim3(HIDDEN / 32, D_MODEL / 32), tb>>>(w1, w1T, D_MODEL, HIDDEN);
    transpose_kernel<<<dim3(HIDDEN / 32, D_MODEL / 32), tb>>>(w2, w2T, D_MODEL, HIDDEN);
    transpose_kernel<<<dim3(D_MODEL / 32, HIDDEN / 32), tb>>>(w3, w3T, HIDDEN, D_MODEL);

    // 1. h = rmsnorm(x, g1)
    rmsnorm_kernel<<<BT, 256>>>(x, g1, h);

    // 2. q/k/v projections (tensor core tf32)
    tc_gemm<<<dim3(D_MODEL / 128, BT / 128), 256, GEMM_SMEM_BYTES>>>(h, wqT, nullptr, q, BT, D_MODEL, D_MODEL, 0);
    tc_gemm<<<dim3((N_KV * HEAD_DIM) / 128, BT / 128), 256, GEMM_SMEM_BYTES>>>(h, wkT, nullptr, k, BT, N_KV * HEAD_DIM, D_MODEL, 0);
    tc_gemm<<<dim3((N_KV * HEAD_DIM) / 128, BT / 128), 256, GEMM_SMEM_BYTES>>>(h, wvT, nullptr, v, BT, N_KV * HEAD_DIM, D_MODEL, 0);

    // 3. RoPE in place
    rope_kernel<<<BT, 768>>>(q, k);

    // 4. causal GQA attention (tensor cores)
    attn_mma<<<dim3(SEQ / 128, BATCH * N_HEADS), 128, ATTN_SMEM>>>(q, k, v, ao);

    // 5. out-proj + residual: d_out = ao @ wo + x
    tc_gemm<<<dim3(D_MODEL / 128, BT / 128), 256, GEMM_SMEM_BYTES>>>(ao, woT, x, out, BT, D_MODEL, D_MODEL, 1);

    // 6. h2 = rmsnorm(d_out, g2)
    rmsnorm_kernel<<<BT, 256>>>(out, g2, h2);

    // 7. FFN branches
    tc_gemm<<<dim3(HIDDEN / 128, BT / 128), 256, GEMM_SMEM_BYTES>>>(h2, w1T, nullptr, a,  BT, HIDDEN, D_MODEL, 0);
    tc_gemm<<<dim3(HIDDEN / 128, BT / 128), 256, GEMM_SMEM_BYTES>>>(h2, w2T, nullptr, bb, BT, HIDDEN, D_MODEL, 0);

    // 8. a = silu(a) * b
    silu_mul_kernel<<<2048, 256>>>(a, bb, (long)BT * HIDDEN);

    // 9. d_out += a @ w3
    tc_gemm<<<dim3(D_MODEL / 128, BT / 128), 256, GEMM_SMEM_BYTES>>>(a, w3T, out, out, BT, D_MODEL, HIDDEN, 1);
}

// round 5
// speedup vs baseline: 3.8148x; 1.3575x over previous
#include <cuda_runtime.h>
#include <cuda_bf16.h>
#include <math.h>
#include <stdint.h>

// ---------------------------------------------------------------------------
// Problem constants
// ---------------------------------------------------------------------------
#define D_MODEL   1024
#define N_HEADS   16
#define N_KV      8
#define HEAD_DIM  64
#define HIDDEN    4096
#define BATCH     4
#define SEQ       2048
#define BT        (BATCH * SEQ)

// ---------------------------------------------------------------------------
// Scratch (device globals)
// ---------------------------------------------------------------------------
__device__ float g_h  [BT * D_MODEL];
__device__ float g_q  [BT * D_MODEL];
__device__ float g_k  [BT * N_KV * HEAD_DIM];
__device__ float g_v  [BT * N_KV * HEAD_DIM];
__device__ float g_ao [BT * D_MODEL];
__device__ float g_h2 [BT * D_MODEL];
__device__ float g_a  [BT * HIDDEN];
__device__ float g_b  [BT * HIDDEN];

__device__ float g_wqT[D_MODEL * D_MODEL];
__device__ float g_wkT[(N_KV * HEAD_DIM) * D_MODEL];
__device__ float g_wvT[(N_KV * HEAD_DIM) * D_MODEL];
__device__ float g_woT[D_MODEL * D_MODEL];
__device__ float g_w1T[HIDDEN * D_MODEL];
__device__ float g_w2T[HIDDEN * D_MODEL];
__device__ float g_w3T[D_MODEL * HIDDEN];

// ---------------------------------------------------------------------------
// Helpers
// ---------------------------------------------------------------------------
__device__ __forceinline__ uint32_t f2tf32(float x) {
    uint32_t r;
    asm("cvt.rna.tf32.f32 %0, %1;" : "=r"(r) : "f"(x));
    return r;
}

__device__ __forceinline__ void mma_tf32(float* c, const uint32_t* a, const uint32_t* b) {
    asm volatile(
        "mma.sync.aligned.m16n8k8.row.col.f32.tf32.tf32.f32 "
        "{%0,%1,%2,%3}, {%4,%5,%6,%7}, {%8,%9}, {%0,%1,%2,%3};\n"
        : "+f"(c[0]), "+f"(c[1]), "+f"(c[2]), "+f"(c[3])
        : "r"(a[0]), "r"(a[1]), "r"(a[2]), "r"(a[3]), "r"(b[0]), "r"(b[1]));
}

__device__ __forceinline__ uint32_t cvta_s(const void* p) {
    return (uint32_t)__cvta_generic_to_shared(p);
}
__device__ __forceinline__ void cp16(uint32_t dst, const void* src) {
    asm volatile(
        "{ .reg .u64 g; cvta.to.global.u64 g, %1; "
        "cp.async.cg.shared.global [%0], [g], 16; }"
        :: "r"(dst), "l"(src) : "memory");
}
#define CP_COMMIT() asm volatile("cp.async.commit_group;\n" ::: "memory")
#define CP_WAIT1()  asm volatile("cp.async.wait_group 1;\n" ::: "memory")
#define CP_WAIT0()  asm volatile("cp.async.wait_group 0;\n" ::: "memory")

// ---------------------------------------------------------------------------
// tf32 tensor-core GEMM: C[M,N] = A[M,K] @ Bt[N,K]^T (+ residual R)
// CTA: 128 threads, 2x2 warps, warp tile 64x64, BK=32,
// 2-stage cp.async pipeline, raw fp32 operands (MMA truncates to tf32).
// ---------------------------------------------------------------------------
#define BKC   32
#define LDP   36
#define STG_F (128 * LDP)
#define GEMM_SMEM_BYTES (4 * STG_F * 4)     // A0,B0,A1,B1 = 73728 B

__global__ void __launch_bounds__(128, 2)
tc_gemm(const float* __restrict__ A, const float* __restrict__ Bt,
        const float* __restrict__ R, float* __restrict__ C,
        int M, int N, int K, int epi) {
    extern __shared__ float sm[];
    float* Abuf[2] = { sm,             sm + 2 * STG_F };
    float* Bbuf[2] = { sm + STG_F,     sm + 3 * STG_F };

    const int tid  = threadIdx.x;
    const int wid  = tid >> 5;
    const int lane = tid & 31;
    const int wm   = wid >> 1;           // 0..1
    const int wn   = wid & 1;            // 0..1
    const int gr   = lane >> 2;
    const int gc   = lane & 3;
    const int m0 = blockIdx.y << 7;
    const int n0 = blockIdx.x << 7;

    // load mapping: 4 passes; pass p: row = 32p + (tid>>2), 8 floats at (tid&3)*8
    const int lr  = tid >> 2;
    const int lc8 = (tid & 3) << 3;      // float offset 0,8,16,24

    const float* Ag = A  + (long)(m0 + lr) * K + lc8;
    const float* Bg = Bt + (long)(n0 + lr) * K + lc8;

    uint32_t sA[2], sB[2];
    #pragma unroll
    for (int s = 0; s < 2; s++) {
        sA[s] = cvta_s(&Abuf[s][lr * LDP + lc8]);
        sB[s] = cvta_s(&Bbuf[s][lr * LDP + lc8]);
    }
    const uint32_t rowstep = 32 * LDP * 4;      // 32 rows in bytes

    const int NC = K / BKC;

    float acc[4][8][4];
    #pragma unroll
    for (int i = 0; i < 4; i++)
        #pragma unroll
        for (int j = 0; j < 8; j++)
            #pragma unroll
            for (int q = 0; q < 4; q++) acc[i][j][q] = 0.f;

    // issue chunk 0
    {
        #pragma unroll
        for (int p = 0; p < 4; p++) {
            cp16(sA[0] + p * rowstep,      Ag + (long)(p * 32) * K);
            cp16(sA[0] + p * rowstep + 16, Ag + (long)(p * 32) * K + 4);
            cp16(sB[0] + p * rowstep,      Bg + (long)(p * 32) * K);
            cp16(sB[0] + p * rowstep + 16, Bg + (long)(p * 32) * K + 4);
        }
        CP_COMMIT();
    }

    for (int i = 0; i < NC; i++) {
        const int cur = i & 1;
        if (i + 1 < NC) {
            const int nxt = cur ^ 1;
            const long ko = (long)(i + 1) * BKC;
            #pragma unroll
            for (int p = 0; p < 4; p++) {
                cp16(sA[nxt] + p * rowstep,      Ag + (long)(p * 32) * K + ko);
                cp16(sA[nxt] + p * rowstep + 16, Ag + (long)(p * 32) * K + ko + 4);
                cp16(sB[nxt] + p * rowstep,      Bg + (long)(p * 32) * K + ko);
                cp16(sB[nxt] + p * rowstep + 16, Bg + (long)(p * 32) * K + ko + 4);
            }
            CP_COMMIT();
            CP_WAIT1();
        } else {
            CP_WAIT0();
        }
        __syncthreads();

        const uint32_t* As = reinterpret_cast<const uint32_t*>(Abuf[cur]);
        const uint32_t* Bs = reinterpret_cast<const uint32_t*>(Bbuf[cur]);

        #pragma unroll
        for (int ks = 0; ks < 4; ks++) {
            const int k0 = ks * 8 + gc;
            uint32_t af[4][4], bf[8][2];
            #pragma unroll
            for (int mt = 0; mt < 4; mt++) {
                const int r = wm * 64 + mt * 16 + gr;
                af[mt][0] = As[r * LDP + k0];
                af[mt][1] = As[(r + 8) * LDP + k0];
                af[mt][2] = As[r * LDP + k0 + 4];
                af[mt][3] = As[(r + 8) * LDP + k0 + 4];
            }
            #pragma unroll
            for (int nt = 0; nt < 8; nt++) {
                const int n = wn * 64 + nt * 8 + gr;
                bf[nt][0] = Bs[n * LDP + k0];
                bf[nt][1] = Bs[n * LDP + k0 + 4];
            }
            #pragma unroll
            for (int mt = 0; mt < 4; mt++)
                #pragma unroll
                for (int nt = 0; nt < 8; nt++)
                    mma_tf32(acc[mt][nt], af[mt], bf[nt]);
        }
        __syncthreads();
    }

    #pragma unroll
    for (int mt = 0; mt < 4; mt++) {
        #pragma unroll
        for (int nt = 0; nt < 8; nt++) {
            const int row = m0 + wm * 64 + mt * 16 + gr;
            const int col = n0 + wn * 64 + nt * 8 + gc * 2;
            float2 lo = make_float2(acc[mt][nt][0], acc[mt][nt][1]);
            float2 hi = make_float2(acc[mt][nt][2], acc[mt][nt][3]);
            if (epi) {
                float2 r0 = *reinterpret_cast<const float2*>(R + (long)row * N + col);
                float2 r1 = *reinterpret_cast<const float2*>(R + (long)(row + 8) * N + col);
                lo.x += r0.x; lo.y += r0.y;
                hi.x += r1.x; hi.y += r1.y;
            }
            *reinterpret_cast<float2*>(C + (long)row * N + col) = lo;
            *reinterpret_cast<float2*>(C + (long)(row + 8) * N + col) = hi;
        }
    }
}

// ---------------------------------------------------------------------------
// Tensor-core flash attention (tf32 mma), causal GQA.
// Raw fp32 operands; 1/8 scale folded into exp args. Double-buffered K/V via
// cp.async. CTA 128 threads, 128 Q rows.
// ---------------------------------------------------------------------------
#define QS_LD 68
#define KS_LD 68
#define VS_LD 72
#define ATTN_SMEM ((128 * QS_LD + 2 * 64 * KS_LD + 2 * 64 * VS_LD) * 4)

__global__ void __launch_bounds__(128, 2)
attn_mma(const float* __restrict__ q, const float* __restrict__ k,
         const float* __restrict__ v, float* __restrict__ o) {
    extern __shared__ uint32_t smu[];
    uint32_t* Qs = smu;
    uint32_t* Kb[2] = { smu + 128 * QS_LD, smu + 128 * QS_LD + 64 * KS_LD };
    uint32_t* Vb[2] = { Kb[1] + 64 * KS_LD, Kb[1] + 64 * KS_LD + 64 * VS_LD };

    const int tid  = threadIdx.x;
    const int warp = tid >> 5;
    const int lane = tid & 31;
    const int gr = lane >> 2;
    const int gc = lane & 3;
    const int wr = warp << 5;

    const int t0  = blockIdx.x << 7;
    const int bh  = blockIdx.y;
    const int b   = bh >> 4;
    const int hq  = bh & 15;
    const int kvh = hq >> 1;

    const long kvstride = N_KV * HEAD_DIM;
    // KV load mapping: thread t -> row t>>1, 32-float half (t&1)
    const int krow = tid >> 1;
    const int kc   = (tid & 1) << 5;     // 0 or 32 floats
    const float* Kg = k + (long)(b * SEQ + krow) * kvstride + kvh * HEAD_DIM + kc;
    const float* Vg = v + (long)(b * SEQ + krow) * kvstride + kvh * HEAD_DIM + kc;
    uint32_t sK[2], sV[2];
    #pragma unroll
    for (int s = 0; s < 2; s++) {
        sK[s] = cvta_s(&Kb[s][krow * KS_LD + kc]);
        sV[s] = cvta_s(&Vb[s][krow * VS_LD + kc]);
    }

    // Q load via cp.async: pass p: row = 32p + (tid>>2), 16 floats at (t&3)*16
    {
        const int qr = tid >> 2;
        const int qc = (tid & 3) << 4;
        const float* Qg = q + (long)(b * SEQ + t0 + qr) * D_MODEL + hq * HEAD_DIM + qc;
        uint32_t dq = cvta_s(&Qs[qr * QS_LD + qc]);
        #pragma unroll
        for (int p = 0; p < 4; p++) {
            #pragma unroll
            for (int u = 0; u < 4; u++)
                cp16(dq + p * 32 * QS_LD * 4 + u * 16,
                     Qg + (long)(p * 32) * D_MODEL + u * 4);
        }
    }
    // issue KV tile 0 (same commit group as Q)
    {
        #pragma unroll
        for (int u = 0; u < 8; u++) {
            cp16(sK[0] + u * 16, Kg + u * 4);
            cp16(sV[0] + u * 16, Vg + u * 4);
        }
        CP_COMMIT();
    }

    float ofrag[2][8][4];
    #pragma unroll
    for (int mt = 0; mt < 2; mt++)
        #pragma unroll
        for (int nt = 0; nt < 8; nt++)
            #pragma unroll
            for (int r = 0; r < 4; r++) ofrag[mt][nt][r] = 0.f;

    float mrow[2][2] = {{-1e30f, -1e30f}, {-1e30f, -1e30f}};
    float lrow[2][2] = {{0.f, 0.f}, {0.f, 0.f}};
    const float SC = 0.125f;             // 1/sqrt(64)

    const int ntiles = (t0 >> 6) + 2;
    for (int it = 0; it < ntiles; it++) {
        const int s0 = it << 6;
        const int cur = it & 1;

        if (it + 1 < ntiles) {
            const int nxt = cur ^ 1;
            const long off = (long)((it + 1) << 6) * kvstride;
            #pragma unroll
            for (int u = 0; u < 8; u++) {
                cp16(sK[nxt] + u * 16, Kg + off + u * 4);
                cp16(sV[nxt] + u * 16, Vg + off + u * 4);
            }
            CP_COMMIT();
            CP_WAIT1();
        } else {
            CP_WAIT0();
        }
        __syncthreads();

        const uint32_t* Ks = Kb[cur];
        const uint32_t* Vs = Vb[cur];

        // ---- S = Q @ K^T (raw fp32 -> tf32 truncation) ----
        float sfrag[2][8][4];
        #pragma unroll
        for (int mt = 0; mt < 2; mt++)
            #pragma unroll
            for (int nt = 0; nt < 8; nt++)
                #pragma unroll
                for (int r = 0; r < 4; r++) sfrag[mt][nt][r] = 0.f;

        #pragma unroll
        for (int ks = 0; ks < 8; ks++) {
            const int k0 = ks * 8 + gc;
            uint32_t aq[2][4];
            #pragma unroll
            for (int mt = 0; mt < 2; mt++) {
                const int r = wr + mt * 16 + gr;
                aq[mt][0] = Qs[r * QS_LD + k0];
                aq[mt][1] = Qs[(r + 8) * QS_LD + k0];
                aq[mt][2] = Qs[r * QS_LD + k0 + 4];
                aq[mt][3] = Qs[(r + 8) * QS_LD + k0 + 4];
            }
            #pragma unroll
            for (int nt = 0; nt < 8; nt++) {
                uint32_t bk[2];
                bk[0] = Ks[(nt * 8 + gr) * KS_LD + k0];
                bk[1] = Ks[(nt * 8 + gr) * KS_LD + k0 + 4];
                mma_tf32(sfrag[0][nt], aq[0], bk);
                mma_tf32(sfrag[1][nt], aq[1], bk);
            }
        }

        // ---- causal mask (diagonal tiles only) ----
        if (it >= ntiles - 2) {
            #pragma unroll
            for (int mt = 0; mt < 2; mt++) {
                const int rA = t0 + wr + mt * 16 + gr;
                const int rB = rA + 8;
                #pragma unroll
                for (int nt = 0; nt < 8; nt++) {
                    const int cb = s0 + nt * 8 + 2 * gc;
                    if (cb     > rA) sfrag[mt][nt][0] = -1e30f;
                    if (cb + 1 > rA) sfrag[mt][nt][1] = -1e30f;
                    if (cb     > rB) sfrag[mt][nt][2] = -1e30f;
                    if (cb + 1 > rB) sfrag[mt][nt][3] = -1e30f;
                }
            }
        }

        // ---- online softmax (scale folded into exp) ----
        #pragma unroll
        for (int mt = 0; mt < 2; mt++) {
            float r0 = -1e30f, r1 = -1e30f;
            #pragma unroll
            for (int nt = 0; nt < 8; nt++) {
                r0 = fmaxf(r0, fmaxf(sfrag[mt][nt][0], sfrag[mt][nt][1]));
                r1 = fmaxf(r1, fmaxf(sfrag[mt][nt][2], sfrag[mt][nt][3]));
            }
            r0 = fmaxf(r0, __shfl_xor_sync(0xffffffffu, r0, 1));
            r0 = fmaxf(r0, __shfl_xor_sync(0xffffffffu, r0, 2));
            r1 = fmaxf(r1, __shfl_xor_sync(0xffffffffu, r1, 1));
            r1 = fmaxf(r1, __shfl_xor_sync(0xffffffffu, r1, 2));

            const float mn0 = fmaxf(mrow[mt][0], r0);
            const float mn1 = fmaxf(mrow[mt][1], r1);
            const float c0 = __expf((mrow[mt][0] - mn0) * SC);
            const float c1 = __expf((mrow[mt][1] - mn1) * SC);
            lrow[mt][0] *= c0;
            lrow[mt][1] *= c1;
            #pragma unroll
            for (int nt = 0; nt < 8; nt++) {
                ofrag[mt][nt][0] *= c0; ofrag[mt][nt][1] *= c0;
                ofrag[mt][nt][2] *= c1; ofrag[mt][nt][3] *= c1;
            }
            float s0s = 0.f, s1s = 0.f;
            #pragma unroll
            for (int nt = 0; nt < 8; nt++) {
                sfrag[mt][nt][0] = __expf((sfrag[mt][nt][0] - mn0) * SC);
                sfrag[mt][nt][1] = __expf((sfrag[mt][nt][1] - mn0) * SC);
                sfrag[mt][nt][2] = __expf((sfrag[mt][nt][2] - mn1) * SC);
                sfrag[mt][nt][3] = __expf((sfrag[mt][nt][3] - mn1) * SC);
                s0s += sfrag[mt][nt][0] + sfrag[mt][nt][1];
                s1s += sfrag[mt][nt][2] + sfrag[mt][nt][3];
            }
            s0s += __shfl_xor_sync(0xffffffffu, s0s, 1);
            s0s += __shfl_xor_sync(0xffffffffu, s0s, 2);
            s1s += __shfl_xor_sync(0xffffffffu, s1s, 1);
            s1s += __shfl_xor_sync(0xffffffffu, s1s, 2);
            lrow[mt][0] += s0s;
            lrow[mt][1] += s1s;
            mrow[mt][0] = mn0;
            mrow[mt][1] = mn1;
        }

        // ---- O += P @ V ----
        const int srcA = (gr << 2) | (gc >> 1);
        const bool odd = gc & 1;
        #pragma unroll
        for (int ks = 0; ks < 8; ks++) {
            uint32_t ap[2][4];
            #pragma unroll
            for (int mt = 0; mt < 2; mt++) {
                const float p0 = sfrag[mt][ks][0], p1 = sfrag[mt][ks][1];
                const float p2 = sfrag[mt][ks][2], p3 = sfrag[mt][ks][3];
                const float v00 = __shfl_sync(0xffffffffu, p0, srcA);
                const float v01 = __shfl_sync(0xffffffffu, p1, srcA);
                const float v10 = __shfl_sync(0xffffffffu, p0, srcA + 2);
                const float v11 = __shfl_sync(0xffffffffu, p1, srcA + 2);
                const float w00 = __shfl_sync(0xffffffffu, p2, srcA);
                const float w01 = __shfl_sync(0xffffffffu, p3, srcA);
                const float w10 = __shfl_sync(0xffffffffu, p2, srcA + 2);
                const float w11 = __shfl_sync(0xffffffffu, p3, srcA + 2);
                ap[mt][0] = __float_as_uint(odd ? v01 : v00);
                ap[mt][1] = __float_as_uint(odd ? w01 : w00);
                ap[mt][2] = __float_as_uint(odd ? v11 : v10);
                ap[mt][3] = __float_as_uint(odd ? w11 : w10);
            }
            #pragma unroll
            for (int nt = 0; nt < 8; nt++) {
                uint32_t bv2[2];
                bv2[0] = Vs[(ks * 8 + gc) * VS_LD + nt * 8 + gr];
                bv2[1] = Vs[(ks * 8 + gc + 4) * VS_LD + nt * 8 + gr];
                mma_tf32(ofrag[0][nt], ap[0], bv2);
                mma_tf32(ofrag[1][nt], ap[1], bv2);
            }
        }
        __syncthreads();
    }

    // ---- write O ----
    #pragma unroll
    for (int mt = 0; mt < 2; mt++) {
        const int rowA = t0 + wr + mt * 16 + gr;
        const int rowB = rowA + 8;
        const float il0 = 1.0f / lrow[mt][0];
        const float il1 = 1.0f / lrow[mt][1];
        #pragma unroll
        for (int nt = 0; nt < 8; nt++) {
            const int col = hq * HEAD_DIM + nt * 8 + 2 * gc;
            float2 lo = make_float2(ofrag[mt][nt][0] * il0, ofrag[mt][nt][1] * il0);
            float2 hi = make_float2(ofrag[mt][nt][2] * il1, ofrag[mt][nt][3] * il1);
            *reinterpret_cast<float2*>(o + (long)(b * SEQ + rowA) * D_MODEL + col) = lo;
            *reinterpret_cast<float2*>(o + (long)(b * SEQ + rowB) * D_MODEL + col) = hi;
        }
    }
}

// ---------------------------------------------------------------------------
// Transpose + tf32-round (RNA) weights: in [R,C] -> out [C,R]
// ---------------------------------------------------------------------------
__global__ void transpose_kernel(const float* __restrict__ in,
                                 float* __restrict__ out, int R, int C) {
    __shared__ float t[32][33];
    const int c0 = blockIdx.x << 5, r0 = blockIdx.y << 5;
    #pragma unroll
    for (int dy = 0; dy < 32; dy += 8) {
        float vv = in[(long)(r0 + threadIdx.y + dy) * C + c0 + threadIdx.x];
        t[threadIdx.y + dy][threadIdx.x] = __uint_as_float(f2tf32(vv));
    }
    __syncthreads();
    #pragma unroll
    for (int dy = 0; dy < 32; dy += 8) {
        out[(long)(c0 + threadIdx.y + dy) * R + r0 + threadIdx.x] =
            t[threadIdx.x][threadIdx.y + dy];
    }
}

// ---------------------------------------------------------------------------
// RMSNorm
// ---------------------------------------------------------------------------
__global__ void rmsnorm_kernel(const float* __restrict__ x,
                               const float* __restrict__ g,
                               float* __restrict__ out) {
    const int row = blockIdx.x;
    const int tid = threadIdx.x;
    const float* xr = x + (long)row * D_MODEL;
    float4 v = *reinterpret_cast<const float4*>(xr + tid * 4);
    float s = v.x * v.x + v.y * v.y + v.z * v.z + v.w * v.w;

    #pragma unroll
    for (int off = 16; off > 0; off >>= 1)
        s += __shfl_xor_sync(0xffffffffu, s, off);

    __shared__ float red[8];
    if ((tid & 31) == 0) red[tid >> 5] = s;
    __syncthreads();
    float total;
    {
        float t = (tid < 8) ? red[tid] : 0.f;
        #pragma unroll
        for (int off = 4; off > 0; off >>= 1)
            t += __shfl_xor_sync(0xffffffffu, t, off);
        __shared__ float bc;
        if (tid == 0) bc = t;
        __syncthreads();
        total = bc;
    }
    float inv = rsqrtf(total * (1.0f / D_MODEL) + 1e-6f);
    float4 gv = *reinterpret_cast<const float4*>(g + tid * 4);
    float4 o;
    o.x = v.x * inv * gv.x;
    o.y = v.y * inv * gv.y;
    o.z = v.z * inv * gv.z;
    o.w = v.w * inv * gv.w;
    *reinterpret_cast<float4*>(out + (long)row * D_MODEL + tid * 4) = o;
}

// ---------------------------------------------------------------------------
// RoPE (half-split, in place)
// ---------------------------------------------------------------------------
__global__ void rope_kernel(float* __restrict__ q, float* __restrict__ k) {
    const int row = blockIdx.x;
    const int t = row & (SEQ - 1);
    const int tid = threadIdx.x;

    float* ptr;
    int j;
    if (tid < 512) {
        int h = tid >> 5; j = tid & 31;
        ptr = q + (long)row * D_MODEL + h * HEAD_DIM;
    } else {
        int u = tid - 512;
        int h = u >> 5; j = u & 31;
        ptr = k + (long)row * (N_KV * HEAD_DIM) + h * HEAD_DIM;
    }
    float inv = (float)exp(-(double)j / 32.0 * 9.210340371976184);
    float fr = (float)t * inv;
    float c = cosf(fr), s = sinf(fr);
    float x1 = ptr[j], x2 = ptr[j + 32];
    ptr[j]      = x1 * c - x2 * s;
    ptr[j + 32] = x2 * c + x1 * s;
}

// ---------------------------------------------------------------------------
// SiLU(a) * b -> a
// ---------------------------------------------------------------------------
__global__ void silu_mul_kernel(float* __restrict__ a,
                                const float* __restrict__ b, long n) {
    long i = (long)blockIdx.x * blockDim.x + threadIdx.x;
    long stride = (long)gridDim.x * blockDim.x;
    for (; i < n; i += stride) {
        float x = a[i];
        float s = x / (1.0f + expf(-x));
        a[i] = s * b[i];
    }
}

// ---------------------------------------------------------------------------
// Launch
// ---------------------------------------------------------------------------
extern "C" void kernel_launch(void* const* d_in, const int* in_sizes, int n_in,
                              void* d_out, int out_size) {
    const float* x  = (const float*)d_in[0];
    const float* g1 = (const float*)d_in[1];
    const float* g2 = (const float*)d_in[2];
    const float* wq = (const float*)d_in[3];
    const float* wk = (const float*)d_in[4];
    const float* wv = (const float*)d_in[5];
    const float* wo = (const float*)d_in[6];
    const float* w1 = (const float*)d_in[7];
    const float* w2 = (const float*)d_in[8];
    const float* w3 = (const float*)d_in[9];
    float* out = (float*)d_out;

    float *h, *q, *k, *v, *ao, *h2, *a, *bb;
    float *wqT, *wkT, *wvT, *woT, *w1T, *w2T, *w3T;
    cudaGetSymbolAddress((void**)&h,  g_h);
    cudaGetSymbolAddress((void**)&q,  g_q);
    cudaGetSymbolAddress((void**)&k,  g_k);
    cudaGetSymbolAddress((void**)&v,  g_v);
    cudaGetSymbolAddress((void**)&ao, g_ao);
    cudaGetSymbolAddress((void**)&h2, g_h2);
    cudaGetSymbolAddress((void**)&a,  g_a);
    cudaGetSymbolAddress((void**)&bb, g_b);
    cudaGetSymbolAddress((void**)&wqT, g_wqT);
    cudaGetSymbolAddress((void**)&wkT, g_wkT);
    cudaGetSymbolAddress((void**)&wvT, g_wvT);
    cudaGetSymbolAddress((void**)&woT, g_woT);
    cudaGetSymbolAddress((void**)&w1T, g_w1T);
    cudaGetSymbolAddress((void**)&w2T, g_w2T);
    cudaGetSymbolAddress((void**)&w3T, g_w3T);

    cudaFuncSetAttribute(tc_gemm, cudaFuncAttributeMaxDynamicSharedMemorySize,
                         GEMM_SMEM_BYTES);
    cudaFuncSetAttribute(attn_mma, cudaFuncAttributeMaxDynamicSharedMemorySize,
                         ATTN_SMEM);

    dim3 tb(32, 8);
    transpose_kernel<<<dim3(D_MODEL / 32, D_MODEL / 32), tb>>>(wq, wqT, D_MODEL, D_MODEL);
    transpose_kernel<<<dim3((N_KV * HEAD_DIM) / 32, D_MODEL / 32), tb>>>(wk, wkT, D_MODEL, N_KV * HEAD_DIM);
    transpose_kernel<<<dim3((N_KV * HEAD_DIM) / 32, D_MODEL / 32), tb>>>(wv, wvT, D_MODEL, N_KV * HEAD_DIM);
    transpose_kernel<<<dim3(D_MODEL / 32, D_MODEL / 32), tb>>>(wo, woT, D_MODEL, D_MODEL);
    transpose_kernel<<<dim3(HIDDEN / 32, D_MODEL / 32), tb>>>(w1, w1T, D_MODEL, HIDDEN);
    transpose_kernel<<<dim3(HIDDEN / 32, D_MODEL / 32), tb>>>(w2, w2T, D_MODEL, HIDDEN);
    transpose_kernel<<<dim3(D_MODEL / 32, HIDDEN / 32), tb>>>(w3, w3T, HIDDEN, D_MODEL);

    rmsnorm_kernel<<<BT, 256>>>(x, g1, h);

    tc_gemm<<<dim3(D_MODEL / 128, BT / 128), 128, GEMM_SMEM_BYTES>>>(h, wqT, nullptr, q, BT, D_MODEL, D_MODEL, 0);
    tc_gemm<<<dim3((N_KV * HEAD_DIM) / 128, BT / 128), 128, GEMM_SMEM_BYTES>>>(h, wkT, nullptr, k, BT, N_KV * HEAD_DIM, D_MODEL, 0);
    tc_gemm<<<dim3((N_KV * HEAD_DIM) / 128, BT / 128), 128, GEMM_SMEM_BYTES>>>(h, wvT, nullptr, v, BT, N_KV * HEAD_DIM, D_MODEL, 0);

    rope_kernel<<<BT, 768>>>(q, k);

    attn_mma<<<dim3(SEQ / 128, BATCH * N_HEADS), 128, ATTN_SMEM>>>(q, k, v, ao);

    tc_gemm<<<dim3(D_MODEL / 128, BT / 128), 128, GEMM_SMEM_BYTES>>>(ao, woT, x, out, BT, D_MODEL, D_MODEL, 1);

    rmsnorm_kernel<<<BT, 256>>>(out, g2, h2);

    tc_gemm<<<dim3(HIDDEN / 128, BT / 128), 128, GEMM_SMEM_BYTES>>>(h2, w1T, nullptr, a,  BT, HIDDEN, D_MODEL, 0);
    tc_gemm<<<dim3(HIDDEN / 128, BT / 128), 128, GEMM_SMEM_BYTES>>>(h2, w2T, nullptr, bb, BT, HIDDEN, D_MODEL, 0);

    silu_mul_kernel<<<2048, 256>>>(a, bb, (long)BT * HIDDEN);

    tc_gemm<<<dim3(D_MODEL / 128, BT / 128), 128, GEMM_SMEM_BYTES>>>(a, w3T, out, out, BT, D_MODEL, HIDDEN, 1);
}